// round 8
// baseline (speedup 1.0000x reference)
#include <cuda_runtime.h>
#include <cstdint>

#define NCOLS            696     // 16 + 120 + 560
#define ROWS_PER_WARP    32
#define WARPS_PER_BLOCK  4
#define THREADS          128
#define MIN_BLOCKS       3
#define ROW_STRIDE       68      // 64 data words + 4 pad (conflict-free STS.128 & LDS.128)
#define BUF_FLOATS       (ROWS_PER_WARP * ROW_STRIDE)   // 2176 floats = 8704 B
// per block: 4 warps * 2 buffers * 8704 B = 69,632 B dynamic smem

// Dubois t-norm for a,b >= 0:  a*b / max(max(a,b), lambda) == min(a, b, a*b/lambda)
__device__ __forceinline__ float tnorm(float a, float b, float inv_l) {
    return fminf(fminf(a, b), a * b * inv_l);
}

// 256-bit streaming global store (sm_100a+): one instruction, 32 bytes.
__device__ __forceinline__ void stg256_cs(float* p, float4 a, float4 b) {
    asm volatile(
        "st.global.cs.v8.f32 [%0], {%1,%2,%3,%4,%5,%6,%7,%8};"
        :: "l"(p),
           "f"(a.x), "f"(a.y), "f"(a.z), "f"(a.w),
           "f"(b.x), "f"(b.y), "f"(b.z), "f"(b.w)
        : "memory");
}

// Pack values for columns [LO,HI) of this lane's row into its warp buffer row
// (wbuf[lane*ROW_STRIDE + (col-LO)]) using STS.128 every 4 columns.
// col/rel are compile-time constants; out-of-range work is DCE'd.
template<int LO, int HI>
__device__ __forceinline__ void compute_chunk(const float xv[16], float inv_l,
                                              float* __restrict__ wbuf, int lane) {
    float4 acc;
    float* rowp = wbuf + lane * ROW_STRIDE;

    int col = 0;
    #define EMIT(VAL)                                                           \
        do {                                                                    \
            if (col >= LO && col < HI) {                                        \
                int rel = col - LO;                                             \
                if ((rel & 3) == 0) acc.x = (VAL);                              \
                else if ((rel & 3) == 1) acc.y = (VAL);                         \
                else if ((rel & 3) == 2) acc.z = (VAL);                         \
                else {                                                          \
                    acc.w = (VAL);                                              \
                    *reinterpret_cast<float4*>(rowp + (rel - 3)) = acc;         \
                }                                                               \
            }                                                                   \
            col++;                                                              \
        } while (0)

    #pragma unroll
    for (int i = 0; i < 16; i++) EMIT(xv[i]);                    // singles 0..15

    #pragma unroll
    for (int i = 0; i < 16; i++) {                               // pairs 16..135
        #pragma unroll
        for (int j = i + 1; j < 16; j++) EMIT(tnorm(xv[i], xv[j], inv_l));
    }

    #pragma unroll
    for (int i = 0; i < 16; i++) {                               // triples 136..695
        #pragma unroll
        for (int j = i + 1; j < 16; j++) {
            float p = tnorm(xv[i], xv[j], inv_l);                // dead if no k in range
            #pragma unroll
            for (int k = j + 1; k < 16; k++) EMIT(tnorm(p, xv[k], inv_l));
        }
    }
    #undef EMIT
}

// Coalesced writeout of columns [LO,HI) for this warp's 32 rows.
// Per lane per iteration: 2x LDS.128 (conflict-free) + 1x 256-bit STG.
// All global addresses are 32B-aligned (row stride 2784B = 87*32, LO*4 % 32 == 0).
template<int LO, int HI>
__device__ __forceinline__ void writeout_chunk(const float* __restrict__ wbuf,
                                               float* __restrict__ out,
                                               int wrow0, int lane) {
    constexpr int NG = (HI - LO) / 8;   // 8-float groups per row (8 or 7)
    #pragma unroll
    for (int it = 0; it < NG; it++) {
        int idx = it * 32 + lane;
        int g = idx % NG;               // group within chunk (fast with lane)
        int r = idx / NG;               // row within warp's 32 rows
        const float* s = wbuf + r * ROW_STRIDE + 8 * g;
        float4 v0 = *reinterpret_cast<const float4*>(s);
        float4 v1 = *reinterpret_cast<const float4*>(s + 4);
        stg256_cs(out + (size_t)(wrow0 + r) * NCOLS + LO + 8 * g, v0, v1);
    }
}

__global__ void __launch_bounds__(THREADS, MIN_BLOCKS)
dubois_kernel(const float* __restrict__ x,
              const float* __restrict__ lambda_,
              float* __restrict__ out) {
    extern __shared__ float smem[];

    const int lane = threadIdx.x & 31;
    const int wid  = threadIdx.x >> 5;
    float* bufA = smem + wid * 2 * BUF_FLOATS;
    float* bufB = bufA + BUF_FLOATS;

    const int wrow0 = blockIdx.x * (ROWS_PER_WARP * WARPS_PER_BLOCK) + wid * ROWS_PER_WARP;
    const int row   = wrow0 + lane;

    const float inv_l = 1.0f / __ldg(lambda_);

    // Load this lane's 16 inputs into registers (4x LDG.128).
    float xv[16];
    const float4* xp = reinterpret_cast<const float4*>(x) + (size_t)row * 4;
    float4 a = xp[0], b = xp[1], c = xp[2], d = xp[3];
    xv[0]=a.x;  xv[1]=a.y;  xv[2]=a.z;  xv[3]=a.w;
    xv[4]=b.x;  xv[5]=b.y;  xv[6]=b.z;  xv[7]=b.w;
    xv[8]=c.x;  xv[9]=c.y;  xv[10]=c.z; xv[11]=c.w;
    xv[12]=d.x; xv[13]=d.y; xv[14]=d.z; xv[15]=d.w;

    // Software pipeline, per-warp double buffer:
    //   step s: writeout(chunk s-1) interleaved with compute(chunk s).
    compute_chunk<0, 64>(xv, inv_l, bufA, lane);
    __syncwarp();

#define STEP(PLO, PHI, CLO, CHI, WB, CB)                         \
    writeout_chunk<PLO, PHI>(WB, out, wrow0, lane);              \
    compute_chunk<CLO, CHI>(xv, inv_l, CB, lane);                \
    __syncwarp();

    STEP(0,   64,  64,  128, bufA, bufB)
    STEP(64,  128, 128, 192, bufB, bufA)
    STEP(128, 192, 192, 256, bufA, bufB)
    STEP(192, 256, 256, 320, bufB, bufA)
    STEP(256, 320, 320, 384, bufA, bufB)
    STEP(320, 384, 384, 448, bufB, bufA)
    STEP(384, 448, 448, 512, bufA, bufB)
    STEP(448, 512, 512, 576, bufB, bufA)
    STEP(512, 576, 576, 640, bufA, bufB)
    STEP(576, 640, 640, 696, bufB, bufA)
#undef STEP

    writeout_chunk<640, 696>(bufA, out, wrow0, lane);
}

extern "C" void kernel_launch(void* const* d_in, const int* in_sizes, int n_in,
                              void* d_out, int out_size) {
    const float* x   = (const float*)d_in[0];
    const float* lam = (const float*)d_in[1];
    float* out = (float*)d_out;

    const int SMEM_BYTES = WARPS_PER_BLOCK * 2 * BUF_FLOATS * sizeof(float); // 69,632
    cudaFuncSetAttribute(dubois_kernel, cudaFuncAttributeMaxDynamicSharedMemorySize,
                         SMEM_BYTES);

    int rows = in_sizes[0] / 16;                                  // 131072
    int grid = rows / (ROWS_PER_WARP * WARPS_PER_BLOCK);          // 1024
    dubois_kernel<<<grid, THREADS, SMEM_BYTES>>>(x, lam, out);
}

// round 9
// speedup vs baseline: 1.0541x; 1.0541x over previous
#include <cuda_runtime.h>
#include <cstdint>

#define NCOLS            696     // 16 + 120 + 560
#define ROWS_PER_WARP    32
#define WARPS_PER_BLOCK  4
#define THREADS          128
#define MIN_BLOCKS       3
#define ROW_STRIDE       68      // 272B lane stride: 17 16B-units, odd -> conflict-free STS.128
#define BUF_FLOATS       (ROWS_PER_WARP * ROW_STRIDE)   // 2176 floats = 8704 B
// per block: 4 warps * 2 buffers * 8704 B = 69,632 B dynamic smem

// Dubois t-norm for a,b >= 0:  a*b / max(max(a,b), lambda) == min(a, b, a*b/lambda)
__device__ __forceinline__ float tnorm(float a, float b, float inv_l) {
    return fminf(fminf(a, b), a * b * inv_l);
}

__device__ __forceinline__ uint32_t smem_u32(const void* p) {
    return (uint32_t)__cvta_generic_to_shared(p);
}

// Pack values for columns [LO,HI) of this lane's row into its PRIVATE smem row
// (wbuf + lane*ROW_STRIDE) using STS.128 every 4 columns.
// col/rel are compile-time constants; out-of-range work is DCE'd.
template<int LO, int HI>
__device__ __forceinline__ void compute_chunk(const float xv[16], float inv_l,
                                              float* __restrict__ rowp) {
    float4 acc;

    int col = 0;
    #define EMIT(VAL)                                                           \
        do {                                                                    \
            if (col >= LO && col < HI) {                                        \
                int rel = col - LO;                                             \
                if ((rel & 3) == 0) acc.x = (VAL);                              \
                else if ((rel & 3) == 1) acc.y = (VAL);                         \
                else if ((rel & 3) == 2) acc.z = (VAL);                         \
                else {                                                          \
                    acc.w = (VAL);                                              \
                    *reinterpret_cast<float4*>(rowp + (rel - 3)) = acc;         \
                }                                                               \
            }                                                                   \
            col++;                                                              \
        } while (0)

    #pragma unroll
    for (int i = 0; i < 16; i++) EMIT(xv[i]);                    // singles 0..15

    #pragma unroll
    for (int i = 0; i < 16; i++) {                               // pairs 16..135
        #pragma unroll
        for (int j = i + 1; j < 16; j++) EMIT(tnorm(xv[i], xv[j], inv_l));
    }

    #pragma unroll
    for (int i = 0; i < 16; i++) {                               // triples 136..695
        #pragma unroll
        for (int j = i + 1; j < 16; j++) {
            float p = tnorm(xv[i], xv[j], inv_l);                // dead if no k in range
            #pragma unroll
            for (int k = j + 1; k < 16; k++) EMIT(tnorm(p, xv[k], inv_l));
        }
    }
    #undef EMIT
}

// Per-lane async bulk store of this lane's staged row segment: one 256B (or
// 224B) cp.async.bulk, smem -> gmem, handled by the TMA engine (no LDS/STG).
// fence.proxy.async orders this thread's STS before the async-proxy read.
// wait_group.read 1 bounds outstanding groups so the other buffer is reusable.
template<int LO, int HI, bool WAIT>
__device__ __forceinline__ void store_row_async(const float* __restrict__ rowp,
                                                float* __restrict__ gdst) {
    constexpr int NBYTES = (HI - LO) * 4;   // 256 or 224, multiple of 16
    asm volatile("fence.proxy.async.shared::cta;" ::: "memory");
    asm volatile(
        "cp.async.bulk.global.shared::cta.bulk_group [%0], [%1], %2;"
        :: "l"(gdst), "r"(smem_u32(rowp)), "n"(NBYTES)
        : "memory");
    asm volatile("cp.async.bulk.commit_group;" ::: "memory");
    if (WAIT)
        asm volatile("cp.async.bulk.wait_group.read 1;" ::: "memory");
}

__global__ void __launch_bounds__(THREADS, MIN_BLOCKS)
dubois_kernel(const float* __restrict__ x,
              const float* __restrict__ lambda_,
              float* __restrict__ out) {
    extern __shared__ float smem[];

    const int lane = threadIdx.x & 31;
    const int wid  = threadIdx.x >> 5;
    // Lane-private staging rows in two buffers (no cross-lane sharing -> no syncs).
    float* rowA = smem + wid * 2 * BUF_FLOATS + lane * ROW_STRIDE;
    float* rowB = rowA + BUF_FLOATS;

    const int wrow0 = blockIdx.x * (ROWS_PER_WARP * WARPS_PER_BLOCK) + wid * ROWS_PER_WARP;
    const int row   = wrow0 + lane;

    const float inv_l = 1.0f / __ldg(lambda_);

    // Load this lane's 16 inputs into registers (4x LDG.128).
    float xv[16];
    const float4* xp = reinterpret_cast<const float4*>(x) + (size_t)row * 4;
    float4 a = xp[0], b = xp[1], c = xp[2], d = xp[3];
    xv[0]=a.x;  xv[1]=a.y;  xv[2]=a.z;  xv[3]=a.w;
    xv[4]=b.x;  xv[5]=b.y;  xv[6]=b.z;  xv[7]=b.w;
    xv[8]=c.x;  xv[9]=c.y;  xv[10]=c.z; xv[11]=c.w;
    xv[12]=d.x; xv[13]=d.y; xv[14]=d.z; xv[15]=d.w;

    float* grow = out + (size_t)row * NCOLS;   // this lane's output row

    // Per-lane software pipeline over 11 column chunks, double-buffered:
    //   compute chunk s into buffer (s&1), async-store it, wait_group.read 1
    //   so buffer (s-1)&1 is free for chunk s+1. No warp/block syncs needed.
    compute_chunk<0, 64>(xv, inv_l, rowA);

#define STEP(PLO, PHI, CLO, CHI, PB, CB)                         \
    store_row_async<PLO, PHI, true>(PB, grow + PLO);             \
    compute_chunk<CLO, CHI>(xv, inv_l, CB);

    STEP(0,   64,  64,  128, rowA, rowB)
    STEP(64,  128, 128, 192, rowB, rowA)
    STEP(128, 192, 192, 256, rowA, rowB)
    STEP(192, 256, 256, 320, rowB, rowA)
    STEP(256, 320, 320, 384, rowA, rowB)
    STEP(320, 384, 384, 448, rowB, rowA)
    STEP(384, 448, 448, 512, rowA, rowB)
    STEP(448, 512, 512, 576, rowB, rowA)
    STEP(512, 576, 576, 640, rowA, rowB)
    STEP(576, 640, 640, 696, rowB, rowA)
#undef STEP

    // Final chunk: no wait needed — async bulk writes are guaranteed complete
    // before grid completion (same contract R5 relied on; correctness passed).
    store_row_async<640, 696, false>(rowA, grow + 640);
}

extern "C" void kernel_launch(void* const* d_in, const int* in_sizes, int n_in,
                              void* d_out, int out_size) {
    const float* x   = (const float*)d_in[0];
    const float* lam = (const float*)d_in[1];
    float* out = (float*)d_out;

    const int SMEM_BYTES = WARPS_PER_BLOCK * 2 * BUF_FLOATS * sizeof(float); // 69,632
    cudaFuncSetAttribute(dubois_kernel, cudaFuncAttributeMaxDynamicSharedMemorySize,
                         SMEM_BYTES);

    int rows = in_sizes[0] / 16;                                  // 131072
    int grid = rows / (ROWS_PER_WARP * WARPS_PER_BLOCK);          // 1024
    dubois_kernel<<<grid, THREADS, SMEM_BYTES>>>(x, lam, out);
}

// round 10
// speedup vs baseline: 1.2504x; 1.1863x over previous
#include <cuda_runtime.h>

#define NCOLS            696     // 16 + 120 + 560
#define NQ_TOTAL         174     // NCOLS / 4
#define ROWS_PER_WARP    32
#define THREADS          128     // warps 0,1 = producers; warps 2,3 = consumers
#define MIN_BLOCKS       3
#define ROW_STRIDE       68      // 64 data words + 4 pad (conflict-free STS.128 & LDS.128)
#define BUF_FLOATS       (ROWS_PER_WARP * ROW_STRIDE)   // 2176 floats = 8704 B
// smem: 2 producers * 2 buffers * 8704 B = 34,816 B static

// Dubois t-norm for a,b >= 0:  a*b / max(max(a,b), lambda) == min(a, b, a*b/lambda)
__device__ __forceinline__ float tnorm(float a, float b, float inv_l) {
    return fminf(fminf(a, b), a * b * inv_l);
}

// Pack values for columns [LO,HI) of this lane's row into its warp buffer row
// using STS.128 every 4 columns. col/rel are compile-time constants.
template<int LO, int HI>
__device__ __forceinline__ void compute_chunk(const float xv[16], float inv_l,
                                              float* __restrict__ wbuf, int lane) {
    float4 acc;
    float* rowp = wbuf + lane * ROW_STRIDE;

    int col = 0;
    #define EMIT(VAL)                                                           \
        do {                                                                    \
            if (col >= LO && col < HI) {                                        \
                int rel = col - LO;                                             \
                if ((rel & 3) == 0) acc.x = (VAL);                              \
                else if ((rel & 3) == 1) acc.y = (VAL);                         \
                else if ((rel & 3) == 2) acc.z = (VAL);                         \
                else {                                                          \
                    acc.w = (VAL);                                              \
                    *reinterpret_cast<float4*>(rowp + (rel - 3)) = acc;         \
                }                                                               \
            }                                                                   \
            col++;                                                              \
        } while (0)

    #pragma unroll
    for (int i = 0; i < 16; i++) EMIT(xv[i]);                    // singles 0..15

    #pragma unroll
    for (int i = 0; i < 16; i++) {                               // pairs 16..135
        #pragma unroll
        for (int j = i + 1; j < 16; j++) EMIT(tnorm(xv[i], xv[j], inv_l));
    }

    #pragma unroll
    for (int i = 0; i < 16; i++) {                               // triples 136..695
        #pragma unroll
        for (int j = i + 1; j < 16; j++) {
            float p = tnorm(xv[i], xv[j], inv_l);                // dead if no k in range
            #pragma unroll
            for (int k = j + 1; k < 16; k++) EMIT(tnorm(p, xv[k], inv_l));
        }
    }
    #undef EMIT
}

// Consumer: coalesced writeout of columns [LO,HI) for the paired producer's 32 rows.
// LDS.128 conflict-free, STG.128 coalesced.
template<int LO, int HI>
__device__ __forceinline__ void writeout_chunk(const float* __restrict__ wbuf,
                                               float4* __restrict__ out4,
                                               int wrow0, int lane) {
    constexpr int NQ = (HI - LO) / 4;   // 16 or 14 float4s per row in this chunk
    #pragma unroll
    for (int it = 0; it < NQ; it++) {
        int idx = it * 32 + lane;
        int q = idx % NQ;               // quad within chunk (fast with lane)
        int r = idx / NQ;               // row within the 32-row tile
        float4 v = *reinterpret_cast<const float4*>(wbuf + r * ROW_STRIDE + 4 * q);
        __stcs(&out4[(size_t)(wrow0 + r) * NQ_TOTAL + (LO / 4) + q], v);
    }
}

__global__ void __launch_bounds__(THREADS, MIN_BLOCKS)
dubois_kernel(const float* __restrict__ x,
              const float* __restrict__ lambda_,
              float* __restrict__ out) {
    // buf[producer][parity][...]
    __shared__ float buf[2][2][BUF_FLOATS];   // 34,816 B

    const int lane = threadIdx.x & 31;
    const int wid  = threadIdx.x >> 5;
    const bool producer = (wid < 2);
    const int tidx = wid & 1;                 // tile index, pairs warp w with warp w+2

    const int wrow0 = blockIdx.x * (2 * ROWS_PER_WARP) + tidx * ROWS_PER_WARP;
    float4* out4 = reinterpret_cast<float4*>(out);

    float xv[16];
    float inv_l = 0.0f;
    if (producer) {
        inv_l = 1.0f / __ldg(lambda_);
        const int row = wrow0 + lane;
        const float4* xp = reinterpret_cast<const float4*>(x) + (size_t)row * 4;
        float4 a = xp[0], b = xp[1], c = xp[2], d = xp[3];
        xv[0]=a.x;  xv[1]=a.y;  xv[2]=a.z;  xv[3]=a.w;
        xv[4]=b.x;  xv[5]=b.y;  xv[6]=b.z;  xv[7]=b.w;
        xv[8]=c.x;  xv[9]=c.y;  xv[10]=c.z; xv[11]=c.w;
        xv[12]=d.x; xv[13]=d.y; xv[14]=d.z; xv[15]=d.w;
    }

    // Step 0: producers fill chunk 0 into parity-0 buffers.
    if (producer) compute_chunk<0, 64>(xv, inv_l, buf[tidx][0], lane);
    __syncthreads();

    // Steps 1..10: producers compute chunk s into buf[.][s&1] while consumers
    // drain chunk s-1 from buf[.][(s-1)&1]. Store backpressure hits only
    // consumer warps; producer compute streams uninterrupted.
#define STEP(S, PLO, PHI, CLO, CHI)                                        \
    if (producer) compute_chunk<CLO, CHI>(xv, inv_l, buf[tidx][(S) & 1], lane); \
    else          writeout_chunk<PLO, PHI>(buf[tidx][((S) - 1) & 1], out4, wrow0, lane); \
    __syncthreads();

    STEP(1,  0,   64,  64,  128)
    STEP(2,  64,  128, 128, 192)
    STEP(3,  128, 192, 192, 256)
    STEP(4,  192, 256, 256, 320)
    STEP(5,  256, 320, 320, 384)
    STEP(6,  320, 384, 384, 448)
    STEP(7,  384, 448, 448, 512)
    STEP(8,  448, 512, 512, 576)
    STEP(9,  512, 576, 576, 640)
    STEP(10, 576, 640, 640, 696)
#undef STEP

    // Epilogue: drain chunk 10 (parity 0).
    if (!producer) writeout_chunk<640, 696>(buf[tidx][0], out4, wrow0, lane);
}

extern "C" void kernel_launch(void* const* d_in, const int* in_sizes, int n_in,
                              void* d_out, int out_size) {
    const float* x   = (const float*)d_in[0];
    const float* lam = (const float*)d_in[1];
    float* out = (float*)d_out;

    int rows = in_sizes[0] / 16;                  // 131072
    int grid = rows / (2 * ROWS_PER_WARP);        // 2048 blocks, 64 rows each
    dubois_kernel<<<grid, THREADS>>>(x, lam, out);
}

// round 11
// speedup vs baseline: 1.2863x; 1.0287x over previous
#include <cuda_runtime.h>

#define NCOLS            696     // 16 + 120 + 560
#define NQ_TOTAL         174     // NCOLS / 4
#define ROWS_PER_WARP    32
#define THREADS          128     // warps 0,1 = producers; warps 2,3 = consumers
#define MIN_BLOCKS       3
#define ROW_STRIDE       68      // 64 data words + 4 pad (conflict-free STS.128 & LDS.128)
#define BUF_FLOATS       (ROWS_PER_WARP * ROW_STRIDE)   // 2176 floats = 8704 B
// smem: 2 tiles * 2 buffers * 8704 B = 34,816 B static

// Named-barrier producer/consumer protocol, 64 threads (1 producer + 1 consumer warp).
#define BAR_SYNC(ID)   asm volatile("bar.sync %0, 64;"   :: "r"(ID) : "memory")
#define BAR_ARRIVE(ID) asm volatile("bar.arrive %0, 64;" :: "r"(ID) : "memory")

// Dubois t-norm for a,b >= 0:  a*b / max(max(a,b), lambda) == min(a, b, a*b/lambda)
__device__ __forceinline__ float tnorm(float a, float b, float inv_l) {
    return fminf(fminf(a, b), a * b * inv_l);
}

// Pack values for columns [LO,HI) of this lane's row into its warp buffer row
// using STS.128 every 4 columns. col/rel are compile-time constants.
template<int LO, int HI>
__device__ __forceinline__ void compute_chunk(const float xv[16], float inv_l,
                                              float* __restrict__ wbuf, int lane) {
    float4 acc;
    float* rowp = wbuf + lane * ROW_STRIDE;

    int col = 0;
    #define EMIT(VAL)                                                           \
        do {                                                                    \
            if (col >= LO && col < HI) {                                        \
                int rel = col - LO;                                             \
                if ((rel & 3) == 0) acc.x = (VAL);                              \
                else if ((rel & 3) == 1) acc.y = (VAL);                         \
                else if ((rel & 3) == 2) acc.z = (VAL);                         \
                else {                                                          \
                    acc.w = (VAL);                                              \
                    *reinterpret_cast<float4*>(rowp + (rel - 3)) = acc;         \
                }                                                               \
            }                                                                   \
            col++;                                                              \
        } while (0)

    #pragma unroll
    for (int i = 0; i < 16; i++) EMIT(xv[i]);                    // singles 0..15

    #pragma unroll
    for (int i = 0; i < 16; i++) {                               // pairs 16..135
        #pragma unroll
        for (int j = i + 1; j < 16; j++) EMIT(tnorm(xv[i], xv[j], inv_l));
    }

    #pragma unroll
    for (int i = 0; i < 16; i++) {                               // triples 136..695
        #pragma unroll
        for (int j = i + 1; j < 16; j++) {
            float p = tnorm(xv[i], xv[j], inv_l);                // dead if no k in range
            #pragma unroll
            for (int k = j + 1; k < 16; k++) EMIT(tnorm(p, xv[k], inv_l));
        }
    }
    #undef EMIT
}

// Consumer: coalesced writeout of columns [LO,HI) for the paired producer's 32 rows.
// LDS.128 conflict-free, STG.128 coalesced.
template<int LO, int HI>
__device__ __forceinline__ void writeout_chunk(const float* __restrict__ wbuf,
                                               float4* __restrict__ out4,
                                               int wrow0, int lane) {
    constexpr int NQ = (HI - LO) / 4;   // 16 or 14 float4s per row in this chunk
    #pragma unroll
    for (int it = 0; it < NQ; it++) {
        int idx = it * 32 + lane;
        int q = idx % NQ;               // quad within chunk (fast with lane)
        int r = idx / NQ;               // row within the 32-row tile
        float4 v = *reinterpret_cast<const float4*>(wbuf + r * ROW_STRIDE + 4 * q);
        __stcs(&out4[(size_t)(wrow0 + r) * NQ_TOTAL + (LO / 4) + q], v);
    }
}

__global__ void __launch_bounds__(THREADS, MIN_BLOCKS)
dubois_kernel(const float* __restrict__ x,
              const float* __restrict__ lambda_,
              float* __restrict__ out) {
    // buf[tile][parity][...]
    __shared__ float buf[2][2][BUF_FLOATS];   // 34,816 B

    const int lane = threadIdx.x & 31;
    const int wid  = threadIdx.x >> 5;
    const bool producer = (wid < 2);
    const int tidx = wid & 1;                 // tile index: pairs warp w with warp w+2

    // Per-pair named barriers (IDs 1..8): FULL[p] = producer->consumer handoff,
    // FREE[p] = consumer->producer buffer release. 64 threads each.
    const int FULL0 = 1 + 4 * tidx, FULL1 = 2 + 4 * tidx;
    const int FREE0 = 3 + 4 * tidx, FREE1 = 4 + 4 * tidx;

    const int wrow0 = blockIdx.x * (2 * ROWS_PER_WARP) + tidx * ROWS_PER_WARP;
    float4* out4 = reinterpret_cast<float4*>(out);
    float* wbuf0 = buf[tidx][0];
    float* wbuf1 = buf[tidx][1];

    if (producer) {
        const float inv_l = 1.0f / __ldg(lambda_);
        const int row = wrow0 + lane;
        float xv[16];
        const float4* xp = reinterpret_cast<const float4*>(x) + (size_t)row * 4;
        float4 a = xp[0], b = xp[1], c = xp[2], d = xp[3];
        xv[0]=a.x;  xv[1]=a.y;  xv[2]=a.z;  xv[3]=a.w;
        xv[4]=b.x;  xv[5]=b.y;  xv[6]=b.z;  xv[7]=b.w;
        xv[8]=c.x;  xv[9]=c.y;  xv[10]=c.z; xv[11]=c.w;
        xv[12]=d.x; xv[13]=d.y; xv[14]=d.z; xv[15]=d.w;

        // Chunks 0,1: buffers start free.
        compute_chunk<0,  64 >(xv, inv_l, wbuf0, lane);  BAR_ARRIVE(FULL0);
        compute_chunk<64, 128>(xv, inv_l, wbuf1, lane);  BAR_ARRIVE(FULL1);

        // Chunks 2..10: wait for buffer s-2 to be drained, refill, publish.
#define PSTEP(LO, HI, FREE_B, FULL_B, WB)                        \
        BAR_SYNC(FREE_B);                                        \
        compute_chunk<LO, HI>(xv, inv_l, WB, lane);              \
        BAR_ARRIVE(FULL_B);

        PSTEP(128, 192, FREE0, FULL0, wbuf0)
        PSTEP(192, 256, FREE1, FULL1, wbuf1)
        PSTEP(256, 320, FREE0, FULL0, wbuf0)
        PSTEP(320, 384, FREE1, FULL1, wbuf1)
        PSTEP(384, 448, FREE0, FULL0, wbuf0)
        PSTEP(448, 512, FREE1, FULL1, wbuf1)
        PSTEP(512, 576, FREE0, FULL0, wbuf0)
        PSTEP(576, 640, FREE1, FULL1, wbuf1)
        PSTEP(640, 696, FREE0, FULL0, wbuf0)
#undef PSTEP
    } else {
        // Consumer: drain chunks 0..10; release FREE for chunks 0..8 only
        // (chunks 9,10 are never overwritten).
#define CSTEP(LO, HI, FULL_B, WB)                                \
        BAR_SYNC(FULL_B);                                        \
        writeout_chunk<LO, HI>(WB, out4, wrow0, lane);

        CSTEP(0,   64,  FULL0, wbuf0)  BAR_ARRIVE(FREE0);
        CSTEP(64,  128, FULL1, wbuf1)  BAR_ARRIVE(FREE1);
        CSTEP(128, 192, FULL0, wbuf0)  BAR_ARRIVE(FREE0);
        CSTEP(192, 256, FULL1, wbuf1)  BAR_ARRIVE(FREE1);
        CSTEP(256, 320, FULL0, wbuf0)  BAR_ARRIVE(FREE0);
        CSTEP(320, 384, FULL1, wbuf1)  BAR_ARRIVE(FREE1);
        CSTEP(384, 448, FULL0, wbuf0)  BAR_ARRIVE(FREE0);
        CSTEP(448, 512, FULL1, wbuf1)  BAR_ARRIVE(FREE1);
        CSTEP(512, 576, FULL0, wbuf0)  BAR_ARRIVE(FREE0);
        CSTEP(576, 640, FULL1, wbuf1)
        CSTEP(640, 696, FULL0, wbuf0)
#undef CSTEP
    }
}

extern "C" void kernel_launch(void* const* d_in, const int* in_sizes, int n_in,
                              void* d_out, int out_size) {
    const float* x   = (const float*)d_in[0];
    const float* lam = (const float*)d_in[1];
    float* out = (float*)d_out;

    int rows = in_sizes[0] / 16;                  // 131072
    int grid = rows / (2 * ROWS_PER_WARP);        // 2048 blocks, 64 rows each
    dubois_kernel<<<grid, THREADS>>>(x, lam, out);
}